// round 2
// baseline (speedup 1.0000x reference)
#include <cuda_runtime.h>
#include <cuda_bf16.h>
#include <math.h>

#define NN 512
#define CC 256
#define HWP 196          // 14*14
#define CKTOT 2304       // C*9
#define TC 8             // input-channel chunk in smem

// ---------------- scratch (static device globals; no allocation) -------------
__device__ float g_Wc[CKTOT * CC];     // combined char weights   [ck][o]
__device__ float g_Wt[CKTOT * CC];     // combined text weights   [ck][o]
__device__ float g_Wf[CKTOT * CC];     // combined fuse weights   [ck][o]
__device__ float g_branch[NN * CC * HWP]; // branch conv output (103MB)
__device__ int   g_members[NN * NN];   // member lists per proposal
__device__ int   g_cnt[NN];
__device__ float g_inv[NN];

// ---------------- 1) box overlap mask / member lists -------------------------
__global__ void mask_kernel(const float* __restrict__ boxes) {
    int i = blockIdx.x * blockDim.x + threadIdx.x;
    if (i >= NN) return;
    float ax0 = boxes[i * 4 + 0], ay0 = boxes[i * 4 + 1];
    float ax1 = boxes[i * 4 + 2], ay1 = boxes[i * 4 + 3];
    int c = 0;
    for (int j = 0; j < NN; j++) {
        float bx0 = boxes[j * 4 + 0], by0 = boxes[j * 4 + 1];
        float bx1 = boxes[j * 4 + 2], by1 = boxes[j * 4 + 3];
        float ltx = fmaxf(ax0, bx0), lty = fmaxf(ay0, by0);
        float rbx = fminf(ax1, bx1), rby = fminf(ay1, by1);
        float w = fmaxf(rbx - ltx, 0.0f);
        float h = fmaxf(rby - lty, 0.0f);
        float inter = w * h;
        float areaj = (bx1 - bx0) * (by1 - by0);
        if (inter / areaj > 0.9f) { g_members[i * NN + c] = j; c++; }
    }
    g_cnt[i] = c;
    g_inv[i] = 1.0f / (float)c;
}

// ---------------- 2) fold conv1x1 into conv3x3 weights ------------------------
// Wo[ck][o] = sum_m W1[o][m] * W3[m][ck],   ck = c*9 + k
__global__ void combine_kernel(const float* __restrict__ Wc3, const float* __restrict__ Wc1,
                               const float* __restrict__ Wt3, const float* __restrict__ Wt1,
                               const float* __restrict__ Wf3, const float* __restrict__ Wf1) {
    const float *W3, *W1;
    float* Wo;
    if (blockIdx.z == 0)      { W3 = Wc3; W1 = Wc1; Wo = g_Wc; }
    else if (blockIdx.z == 1) { W3 = Wt3; W1 = Wt1; Wo = g_Wt; }
    else                      { W3 = Wf3; W1 = Wf1; Wo = g_Wf; }

    int ckb = blockIdx.x * 32;   // 72 tiles of 32 over 2304
    int ob  = blockIdx.y * 64;   // 4 tiles of 64 over 256
    int tid = threadIdx.x;       // 256 threads
    int ck_l = tid >> 3;         // 0..31
    int og   = tid & 7;          // 0..7 -> 8 contiguous outputs

    __shared__ __align__(16) float As[32 * 32];   // [m][ck]
    __shared__ __align__(16) float Bs[32 * 64];   // [m][o]

    float acc[8];
#pragma unroll
    for (int j = 0; j < 8; j++) acc[j] = 0.0f;

    for (int mb = 0; mb < 256; mb += 32) {
        __syncthreads();
        for (int idx = tid; idx < 1024; idx += 256) {
            int m = idx >> 5, ck = idx & 31;
            As[idx] = W3[(mb + m) * CKTOT + ckb + ck];
        }
        {
            int o  = tid & 63;
            int m8 = (tid >> 6) * 8;
#pragma unroll
            for (int mi = 0; mi < 8; mi++)
                Bs[(m8 + mi) * 64 + o] = W1[(ob + o) * 256 + mb + m8 + mi];
        }
        __syncthreads();
#pragma unroll
        for (int m = 0; m < 32; m++) {
            float a = As[m * 32 + ck_l];
            float b[8];
            *(float4*)&b[0] = *(const float4*)&Bs[m * 64 + og * 8];
            *(float4*)&b[4] = *(const float4*)&Bs[m * 64 + og * 8 + 4];
#pragma unroll
            for (int j = 0; j < 8; j++) acc[j] = fmaf(a, b[j], acc[j]);
        }
    }
    float* po = &Wo[(ckb + ck_l) * 256 + ob + og * 8];
    *(float4*)po       = *(const float4*)&acc[0];
    *(float4*)(po + 4) = *(const float4*)&acc[4];
}

// ---------------- 3) main conv3x3 kernel --------------------------------------
// MODE 0: branch conv. input = (class!=0) ? x[n] : gather-avg ; W = Wc or Wt ; out -> g_branch
// MODE 1: fuse conv.   input = g_branch[n] + x[n] + gc[n]     ; W = Wf        ; out -> d_out (BN+ReLU)
// grid (4 oc-tiles, 512 samples), block 224 threads.
// thread micro-tile: 8 contiguous oc  x  7 contiguous positions.
template <int MODE>
__global__ void __launch_bounds__(224, 2)
conv_kernel(const float* __restrict__ x, const float* __restrict__ gc,
            const int* __restrict__ classes,
            const float* __restrict__ bn_gamma, const float* __restrict__ bn_beta,
            const float* __restrict__ bn_mean,  const float* __restrict__ bn_var,
            float* __restrict__ out) {
    int n  = blockIdx.y;
    int ob = blockIdx.x * 64;
    int tid = threadIdx.x;
    int oc_thr  = tid & 7;   // 0..7  -> ocs ob + oc_thr*8 + i
    int pos_thr = tid >> 3;  // 0..27 -> positions pos_thr*7 + m
    int p0 = pos_thr * 7;

    int base[7];
#pragma unroll
    for (int m = 0; m < 7; m++) {
        int p = p0 + m;
        base[m] = (p / 14) * 16 + (p % 14);
    }

    const float* Wg;
    bool gather = false;
    int mcount = 1;
    float invn = 1.0f;
    const int xbase = n * CC * HWP;
    if (MODE == 0) {
        if (classes[n] != 0) {
            Wg = g_Wc;
        } else {
            Wg = g_Wt;
            int c = g_cnt[n];
            if (c > 1) { gather = true; mcount = c; invn = g_inv[n]; }
        }
    } else {
        Wg = g_Wf;
    }

    __shared__ __align__(16) float Xs[TC * 256];      // padded 16x16 per channel
    __shared__ __align__(16) float Ws[TC * 9 * 64];   // [c_l*9+k][64 oc]

    float acc[8][7];
#pragma unroll
    for (int i = 0; i < 8; i++)
#pragma unroll
        for (int m = 0; m < 7; m++) acc[i][m] = 0.0f;

    for (int cb = 0; cb < CC; cb += TC) {
        __syncthreads();
        // weights: Wg[(cb*9 + ck)][ob + o], ck local in [0, TC*9)
        for (int idx = tid; idx < TC * 9 * 64; idx += 224) {
            int ck = idx >> 6;
            int o  = idx & 63;
            Ws[idx] = Wg[(cb * 9 + ck) * 256 + ob + o];
        }
        // input: zero-padded 16x16 tiles
        for (int idx = tid; idx < TC * 256; idx += 224) {
            int c_l = idx >> 8;
            int pp  = idx & 255;
            int yy = pp >> 4, xx = pp & 15;
            float v = 0.0f;
            if (yy >= 1 && yy < 15 && xx >= 1 && xx < 15) {
                int off = (cb + c_l) * HWP + (yy - 1) * 14 + (xx - 1);
                if (MODE == 0) {
                    if (!gather) {
                        v = x[xbase + off];
                    } else {
                        float s = 0.0f;
                        for (int t = 0; t < mcount; t++)
                            s += x[g_members[n * NN + t] * CC * HWP + off];
                        v = s * invn;
                    }
                } else {
                    int gi = xbase + off;
                    v = g_branch[gi] + x[gi] + gc[gi];
                }
            }
            Xs[idx] = v;
        }
        __syncthreads();

#pragma unroll 2
        for (int c_l = 0; c_l < TC; c_l++) {
#pragma unroll
            for (int k = 0; k < 9; k++) {
                float w[8];
                const float* wp = &Ws[(c_l * 9 + k) * 64 + oc_thr * 8];
                *(float4*)&w[0] = *(const float4*)wp;
                *(float4*)&w[4] = *(const float4*)(wp + 4);
                int dy = k / 3, dx = k % 3;
                int xoff = c_l * 256 + dy * 16 + dx;
                float xv[7];
#pragma unroll
                for (int m = 0; m < 7; m++) xv[m] = Xs[xoff + base[m]];
#pragma unroll
                for (int i = 0; i < 8; i++)
#pragma unroll
                    for (int m = 0; m < 7; m++)
                        acc[i][m] = fmaf(w[i], xv[m], acc[i][m]);
            }
        }
    }

    if (MODE == 0) {
#pragma unroll
        for (int i = 0; i < 8; i++) {
            float* po = &g_branch[xbase + (ob + oc_thr * 8 + i) * HWP + p0];
#pragma unroll
            for (int m = 0; m < 7; m++) po[m] = acc[i][m];
        }
    } else {
        float sc[8], sh[8];
#pragma unroll
        for (int i = 0; i < 8; i++) {
            int o = ob + oc_thr * 8 + i;
            float s = bn_gamma[o] * rsqrtf(bn_var[o] + 1e-5f);
            sc[i] = s;
            sh[i] = bn_beta[o] - bn_mean[o] * s;
        }
#pragma unroll
        for (int i = 0; i < 8; i++) {
            float* po = &out[xbase + (ob + oc_thr * 8 + i) * HWP + p0];
#pragma unroll
            for (int m = 0; m < 7; m++) {
                float v = fmaf(acc[i][m], sc[i], sh[i]);
                po[m] = fmaxf(v, 0.0f);
            }
        }
    }
}

// ---------------- launch ------------------------------------------------------
extern "C" void kernel_launch(void* const* d_in, const int* in_sizes, int n_in,
                              void* d_out, int out_size) {
    const float* x       = (const float*)d_in[0];
    const float* gc      = (const float*)d_in[1];
    const float* boxes   = (const float*)d_in[2];
    const int*   classes = (const int*)  d_in[3];
    const float* Wc3     = (const float*)d_in[4];
    const float* Wc1     = (const float*)d_in[5];
    const float* Wt3     = (const float*)d_in[6];
    const float* Wt1     = (const float*)d_in[7];
    const float* Wf3     = (const float*)d_in[8];
    const float* Wf1     = (const float*)d_in[9];
    const float* bg      = (const float*)d_in[10];
    const float* bb      = (const float*)d_in[11];
    const float* bm      = (const float*)d_in[12];
    const float* bv      = (const float*)d_in[13];
    float* out = (float*)d_out;

    mask_kernel<<<2, 256>>>(boxes);
    combine_kernel<<<dim3(72, 4, 3), 256>>>(Wc3, Wc1, Wt3, Wt1, Wf3, Wf1);
    conv_kernel<0><<<dim3(4, NN), 224>>>(x, gc, classes, bg, bb, bm, bv, nullptr);
    conv_kernel<1><<<dim3(4, NN), 224>>>(x, gc, classes, bg, bb, bm, bv, out);
}

// round 3
// speedup vs baseline: 1.0029x; 1.0029x over previous
#include <cuda_runtime.h>
#include <cuda_bf16.h>
#include <math.h>

#define NN 512
#define CC 256
#define HWP 196          // 14*14
#define CKTOT 2304       // C*9
#define TC 8             // input-channel chunk in smem

// ---------------- scratch (static device globals; no allocation) -------------
__device__ float g_Wc[CKTOT * CC];     // combined char weights   [ck][o]
__device__ float g_Wt[CKTOT * CC];     // combined text weights   [ck][o]
__device__ float g_Wf[CKTOT * CC];     // combined fuse weights   [ck][o]
__device__ float g_branch[NN * CC * HWP]; // branch conv output (103MB)
__device__ int   g_members[NN * NN];   // member lists per proposal
__device__ int   g_cnt[NN];
__device__ float g_inv[NN];

// ---------------- 1) box overlap mask / member lists -------------------------
__global__ void mask_kernel(const float* __restrict__ boxes) {
    int i = blockIdx.x * blockDim.x + threadIdx.x;
    if (i >= NN) return;
    float ax0 = boxes[i * 4 + 0], ay0 = boxes[i * 4 + 1];
    float ax1 = boxes[i * 4 + 2], ay1 = boxes[i * 4 + 3];
    int c = 0;
    for (int j = 0; j < NN; j++) {
        float bx0 = boxes[j * 4 + 0], by0 = boxes[j * 4 + 1];
        float bx1 = boxes[j * 4 + 2], by1 = boxes[j * 4 + 3];
        float ltx = fmaxf(ax0, bx0), lty = fmaxf(ay0, by0);
        float rbx = fminf(ax1, bx1), rby = fminf(ay1, by1);
        float w = fmaxf(rbx - ltx, 0.0f);
        float h = fmaxf(rby - lty, 0.0f);
        float inter = w * h;
        float areaj = (bx1 - bx0) * (by1 - by0);
        if (inter / areaj > 0.9f) { g_members[i * NN + c] = j; c++; }
    }
    g_cnt[i] = c;
    g_inv[i] = 1.0f / (float)c;
}

// ---------------- 2) fold conv1x1 into conv3x3 weights ------------------------
// Wo[ck][o] = sum_m W1[o][m] * W3[m][ck],   ck = c*9 + k
__global__ void combine_kernel(const float* __restrict__ Wc3, const float* __restrict__ Wc1,
                               const float* __restrict__ Wt3, const float* __restrict__ Wt1,
                               const float* __restrict__ Wf3, const float* __restrict__ Wf1) {
    const float *W3, *W1;
    float* Wo;
    if (blockIdx.z == 0)      { W3 = Wc3; W1 = Wc1; Wo = g_Wc; }
    else if (blockIdx.z == 1) { W3 = Wt3; W1 = Wt1; Wo = g_Wt; }
    else                      { W3 = Wf3; W1 = Wf1; Wo = g_Wf; }

    int ckb = blockIdx.x * 32;   // 72 tiles of 32 over 2304
    int ob  = blockIdx.y * 64;   // 4 tiles of 64 over 256
    int tid = threadIdx.x;       // 256 threads
    int ck_l = tid >> 3;         // 0..31
    int og   = tid & 7;          // 0..7 -> 8 contiguous outputs

    __shared__ __align__(16) float As[32 * 32];   // [m][ck]
    __shared__ __align__(16) float Bs[32 * 64];   // [m][o]

    float acc[8];
#pragma unroll
    for (int j = 0; j < 8; j++) acc[j] = 0.0f;

    for (int mb = 0; mb < 256; mb += 32) {
        __syncthreads();
        for (int idx = tid; idx < 1024; idx += 256) {
            int m = idx >> 5, ck = idx & 31;
            As[idx] = W3[(mb + m) * CKTOT + ckb + ck];
        }
        {
            int o  = tid & 63;
            int m8 = (tid >> 6) * 8;
#pragma unroll
            for (int mi = 0; mi < 8; mi++)
                Bs[(m8 + mi) * 64 + o] = W1[(ob + o) * 256 + mb + m8 + mi];
        }
        __syncthreads();
#pragma unroll
        for (int m = 0; m < 32; m++) {
            float a = As[m * 32 + ck_l];
            float b[8];
            *(float4*)&b[0] = *(const float4*)&Bs[m * 64 + og * 8];
            *(float4*)&b[4] = *(const float4*)&Bs[m * 64 + og * 8 + 4];
#pragma unroll
            for (int j = 0; j < 8; j++) acc[j] = fmaf(a, b[j], acc[j]);
        }
    }
    float* po = &Wo[(ckb + ck_l) * 256 + ob + og * 8];
    *(float4*)po       = *(const float4*)&acc[0];
    *(float4*)(po + 4) = *(const float4*)&acc[4];
}

// ---------------- 3) main conv3x3 kernel --------------------------------------
// MODE 0: branch conv. input = (class!=0) ? x[n] : gather-avg ; W = Wc or Wt ; out -> g_branch
// MODE 1: fuse conv.   input = g_branch[n] + x[n] + gc[n]     ; W = Wf        ; out -> d_out (BN+ReLU)
// grid (4 oc-tiles, 512 samples), block 224 threads.
// thread micro-tile: 8 contiguous oc  x  7 contiguous positions.
template <int MODE>
__global__ void __launch_bounds__(224, 2)
conv_kernel(const float* __restrict__ x, const float* __restrict__ gc,
            const int* __restrict__ classes,
            const float* __restrict__ bn_gamma, const float* __restrict__ bn_beta,
            const float* __restrict__ bn_mean,  const float* __restrict__ bn_var,
            float* __restrict__ out) {
    int n  = blockIdx.y;
    int ob = blockIdx.x * 64;
    int tid = threadIdx.x;
    int oc_thr  = tid & 7;   // 0..7  -> ocs ob + oc_thr*8 + i
    int pos_thr = tid >> 3;  // 0..27 -> positions pos_thr*7 + m
    int p0 = pos_thr * 7;

    int base[7];
#pragma unroll
    for (int m = 0; m < 7; m++) {
        int p = p0 + m;
        base[m] = (p / 14) * 16 + (p % 14);
    }

    const float* Wg;
    bool gather = false;
    int mcount = 1;
    float invn = 1.0f;
    const int xbase = n * CC * HWP;
    if (MODE == 0) {
        if (classes[n] != 0) {
            Wg = g_Wc;
        } else {
            Wg = g_Wt;
            int c = g_cnt[n];
            if (c > 1) { gather = true; mcount = c; invn = g_inv[n]; }
        }
    } else {
        Wg = g_Wf;
    }

    __shared__ __align__(16) float Xs[TC * 256];      // padded 16x16 per channel
    __shared__ __align__(16) float Ws[TC * 9 * 64];   // [c_l*9+k][64 oc]

    float acc[8][7];
#pragma unroll
    for (int i = 0; i < 8; i++)
#pragma unroll
        for (int m = 0; m < 7; m++) acc[i][m] = 0.0f;

    for (int cb = 0; cb < CC; cb += TC) {
        __syncthreads();
        // weights: Wg[(cb*9 + ck)][ob + o], ck local in [0, TC*9)
        for (int idx = tid; idx < TC * 9 * 64; idx += 224) {
            int ck = idx >> 6;
            int o  = idx & 63;
            Ws[idx] = Wg[(cb * 9 + ck) * 256 + ob + o];
        }
        // input: zero-padded 16x16 tiles
        for (int idx = tid; idx < TC * 256; idx += 224) {
            int c_l = idx >> 8;
            int pp  = idx & 255;
            int yy = pp >> 4, xx = pp & 15;
            float v = 0.0f;
            if (yy >= 1 && yy < 15 && xx >= 1 && xx < 15) {
                int off = (cb + c_l) * HWP + (yy - 1) * 14 + (xx - 1);
                if (MODE == 0) {
                    if (!gather) {
                        v = x[xbase + off];
                    } else {
                        float s = 0.0f;
                        for (int t = 0; t < mcount; t++)
                            s += x[g_members[n * NN + t] * CC * HWP + off];
                        v = s * invn;
                    }
                } else {
                    int gi = xbase + off;
                    v = g_branch[gi] + x[gi] + gc[gi];
                }
            }
            Xs[idx] = v;
        }
        __syncthreads();

#pragma unroll 2
        for (int c_l = 0; c_l < TC; c_l++) {
#pragma unroll
            for (int k = 0; k < 9; k++) {
                float w[8];
                const float* wp = &Ws[(c_l * 9 + k) * 64 + oc_thr * 8];
                *(float4*)&w[0] = *(const float4*)wp;
                *(float4*)&w[4] = *(const float4*)(wp + 4);
                int dy = k / 3, dx = k % 3;
                int xoff = c_l * 256 + dy * 16 + dx;
                float xv[7];
#pragma unroll
                for (int m = 0; m < 7; m++) xv[m] = Xs[xoff + base[m]];
#pragma unroll
                for (int i = 0; i < 8; i++)
#pragma unroll
                    for (int m = 0; m < 7; m++)
                        acc[i][m] = fmaf(w[i], xv[m], acc[i][m]);
            }
        }
    }

    if (MODE == 0) {
#pragma unroll
        for (int i = 0; i < 8; i++) {
            float* po = &g_branch[xbase + (ob + oc_thr * 8 + i) * HWP + p0];
#pragma unroll
            for (int m = 0; m < 7; m++) po[m] = acc[i][m];
        }
    } else {
        float sc[8], sh[8];
#pragma unroll
        for (int i = 0; i < 8; i++) {
            int o = ob + oc_thr * 8 + i;
            float s = bn_gamma[o] * rsqrtf(bn_var[o] + 1e-5f);
            sc[i] = s;
            sh[i] = bn_beta[o] - bn_mean[o] * s;
        }
#pragma unroll
        for (int i = 0; i < 8; i++) {
            float* po = &out[xbase + (ob + oc_thr * 8 + i) * HWP + p0];
#pragma unroll
            for (int m = 0; m < 7; m++) {
                float v = fmaf(acc[i][m], sc[i], sh[i]);
                po[m] = fmaxf(v, 0.0f);
            }
        }
    }
}

// ---------------- launch ------------------------------------------------------
extern "C" void kernel_launch(void* const* d_in, const int* in_sizes, int n_in,
                              void* d_out, int out_size) {
    const float* x       = (const float*)d_in[0];
    const float* gc      = (const float*)d_in[1];
    const float* boxes   = (const float*)d_in[2];
    const int*   classes = (const int*)  d_in[3];
    const float* Wc3     = (const float*)d_in[4];
    const float* Wc1     = (const float*)d_in[5];
    const float* Wt3     = (const float*)d_in[6];
    const float* Wt1     = (const float*)d_in[7];
    const float* Wf3     = (const float*)d_in[8];
    const float* Wf1     = (const float*)d_in[9];
    const float* bg      = (const float*)d_in[10];
    const float* bb      = (const float*)d_in[11];
    const float* bm      = (const float*)d_in[12];
    const float* bv      = (const float*)d_in[13];
    float* out = (float*)d_out;

    mask_kernel<<<2, 256>>>(boxes);
    combine_kernel<<<dim3(72, 4, 3), 256>>>(Wc3, Wc1, Wt3, Wt1, Wf3, Wf1);
    conv_kernel<0><<<dim3(4, NN), 224>>>(x, gc, classes, bg, bb, bm, bv, nullptr);
    conv_kernel<1><<<dim3(4, NN), 224>>>(x, gc, classes, bg, bb, bm, bv, out);
}